// round 7
// baseline (speedup 1.0000x reference)
#include <cuda_runtime.h>

#define H  64
#define LL 2048
#define VOCAB 64
#define FULL 0xffffffffu

// -------- device-global scratch (no runtime allocation allowed) --------
__device__ __align__(16) float g_ktab[VOCAB * H];    // normalized k per vocab id
__device__ __align__(16) float g_vtab[VOCAB * H];    // v per vocab id
__device__ __align__(16) float g_qtab[VOCAB * H];    // q per vocab id
__device__ __align__(16) float g_KKn[VOCAB * VOCAB]; // NEGATED Gram of k table
__device__ __align__(16) float g_Wcomb[H * H];       // Wout @ Wrp
__device__ __align__(16) float g_bcomb[H];           // Wout @ brp + bout
__device__ unsigned g_bar1 = 0, g_bar2 = 0, g_rst = 0;   // spin barriers

__device__ __forceinline__ float bfly_sum(float v) {
    #pragma unroll
    for (int o = 16; o; o >>= 1) v += __shfl_xor_sync(FULL, v, o);
    return v;
}

// ======================================================================
// Single fused kernel. grid 64, block 128.
//   Phase A: block v encodes vocab v (tables) + Wcomb row v; all warps
//            stage their sequences.                     -> barrier 1
//   Phase B: negated KK row v; every warp computes R-init for one batch
//            (handoff via smem), hiding the barrier-2 wait.
//   Phase C: warps 0-1 scan TWO batches each, statically interleaved so
//            stream B issues inside stream A's stall bubbles; all 4
//            warps split the epilogues.
// ======================================================================
__global__ void __launch_bounds__(128) fused_kernel(
    const int*   __restrict__ seq,
    const float* __restrict__ embed, const float* __restrict__ W1,
    const float* __restrict__ b1, const float* __restrict__ W2,
    const float* __restrict__ b2, const float* __restrict__ gamma,
    const float* __restrict__ beta, const float* __restrict__ Wk,
    const float* __restrict__ Wv, const float* __restrict__ Wq,
    const float* __restrict__ Wrp, const float* __restrict__ brp,
    const float* __restrict__ Wout, const float* __restrict__ bout,
    float* __restrict__ out)
{
    __shared__ __align__(16) float sKKn[VOCAB * H];        // 16 KB
    __shared__ __align__(16) unsigned char sseq[4][LL];    // 8 KB
    __shared__ __align__(16) float e[H], f1[2 * H], h[H], hs[H];
    __shared__ __align__(16) float sRi[4][H];              // R-init handoff
    __shared__ __align__(16) float sS[4][H];               // per-vocab s sums
    __shared__ float s_mu, s_rstd, s_kinv;

    const int v    = blockIdx.x;
    const int tid  = threadIdx.x;
    const int lane = tid & 31;
    const int w    = tid >> 5;
    const int lo2  = 2 * lane;

    // ---- stage this block's 4 sequences (warp w stages batch v*4+w) ----
    {
        const int4* sg = (const int4*)(seq + (v * 4 + w) * LL);
        uchar4* ssh = (uchar4*)sseq[w];
        #pragma unroll 4
        for (int i = lane; i < LL / 4; i += 32) {
            int4 t = sg[i];
            ssh[i] = make_uchar4((unsigned char)t.x, (unsigned char)t.y,
                                 (unsigned char)t.z, (unsigned char)t.w);
        }
    }

    // ================= Phase A: encode vocab v =================
    if (tid < H) e[tid] = embed[v * H + tid];
    __syncthreads();

    {   // ff1 = relu(W1 e + b1)
        const float4* w4 = (const float4*)(W1 + tid * H);
        const float4* e4 = (const float4*)e;
        float a0 = 0.f, a1 = 0.f, a2 = 0.f, a3 = 0.f;
        #pragma unroll
        for (int i = 0; i < 16; i++) {
            float4 ww = w4[i], ee = e4[i];
            a0 = fmaf(ww.x, ee.x, a0); a1 = fmaf(ww.y, ee.y, a1);
            a2 = fmaf(ww.z, ee.z, a2); a3 = fmaf(ww.w, ee.w, a3);
        }
        f1[tid] = fmaxf((a0 + a1) + (a2 + a3) + b1[tid], 0.0f);
    }
    __syncthreads();

    if (tid < H) {   // h = e + W2 ff1 + b2
        const float4* w4 = (const float4*)(W2 + tid * 2 * H);
        const float4* f4 = (const float4*)f1;
        float a0 = 0.f, a1 = 0.f, a2 = 0.f, a3 = 0.f;
        float b0 = 0.f, c1 = 0.f, c2 = 0.f, b3 = 0.f;
        #pragma unroll
        for (int i = 0; i < 32; i += 2) {
            float4 ww = w4[i], ff = f4[i];
            a0 = fmaf(ww.x, ff.x, a0); a1 = fmaf(ww.y, ff.y, a1);
            a2 = fmaf(ww.z, ff.z, a2); a3 = fmaf(ww.w, ff.w, a3);
            float4 w2_ = w4[i + 1], ff2 = f4[i + 1];
            b0 = fmaf(w2_.x, ff2.x, b0); c1 = fmaf(w2_.y, ff2.y, c1);
            c2 = fmaf(w2_.z, ff2.z, c2); b3 = fmaf(w2_.w, ff2.w, b3);
        }
        h[tid] = e[tid] + ((a0 + a1) + (a2 + a3)) + ((b0 + c1) + (c2 + b3)) + b2[tid];
    }
    __syncthreads();

    if (tid < 32) {   // LayerNorm stats (biased var, eps 1e-5)
        float x = bfly_sum(h[tid] + h[tid + 32]);
        float mu = x * (1.0f / H);
        float c0 = h[tid] - mu, c1_ = h[tid + 32] - mu;
        float vv = bfly_sum(c0 * c0 + c1_ * c1_);
        if (tid == 0) { s_mu = mu; s_rstd = rsqrtf(vv * (1.0f / H) + 1e-5f); }
    }
    __syncthreads();
    if (tid < H) hs[tid] = (h[tid] - s_mu) * s_rstd * gamma[tid] + beta[tid];
    __syncthreads();

    if (tid < H) {   // k (raw) and q projections
        const float4* wk4 = (const float4*)(Wk + tid * H);
        const float4* wq4 = (const float4*)(Wq + tid * H);
        const float4* h4 = (const float4*)hs;
        float k0 = 0.f, k1 = 0.f, k2 = 0.f, k3 = 0.f;
        float q0 = 0.f, q1 = 0.f, q2 = 0.f, q3 = 0.f;
        #pragma unroll
        for (int i = 0; i < 16; i++) {
            float4 wk = wk4[i], wq = wq4[i], hh = h4[i];
            k0 = fmaf(wk.x, hh.x, k0); k1 = fmaf(wk.y, hh.y, k1);
            k2 = fmaf(wk.z, hh.z, k2); k3 = fmaf(wk.w, hh.w, k3);
            q0 = fmaf(wq.x, hh.x, q0); q1 = fmaf(wq.y, hh.y, q1);
            q2 = fmaf(wq.z, hh.z, q2); q3 = fmaf(wq.w, hh.w, q3);
        }
        h[tid] = (k0 + k1) + (k2 + k3);
        g_qtab[v * H + tid] = (q0 + q1) + (q2 + q3);
    } else {         // v projection
        const int i = tid - H;
        const float4* wv4 = (const float4*)(Wv + i * H);
        const float4* h4 = (const float4*)hs;
        float a0 = 0.f, a1 = 0.f, a2 = 0.f, a3 = 0.f;
        #pragma unroll
        for (int j = 0; j < 16; j++) {
            float4 ww = wv4[j], hh = h4[j];
            a0 = fmaf(ww.x, hh.x, a0); a1 = fmaf(ww.y, hh.y, a1);
            a2 = fmaf(ww.z, hh.z, a2); a3 = fmaf(ww.w, hh.w, a3);
        }
        g_vtab[v * H + i] = (a0 + a1) + (a2 + a3);
    }
    __syncthreads();

    if (tid < 32) {   // k normalization
        float n = bfly_sum(h[tid] * h[tid] + h[tid + 32] * h[tid + 32]);
        if (tid == 0) s_kinv = 1.0f / fmaxf(sqrtf(n), 1e-12f);
    }
    __syncthreads();
    if (tid < H) {
        float kv = h[tid] * s_kinv;
        g_ktab[v * H + tid] = kv;
        hs[tid] = kv;                 // keep own k row in smem for KK phase
    }

    // Wcomb row v + bcomb[v]
    if (tid < H) {
        float ww = 0.f, w1_ = 0.f;
        #pragma unroll
        for (int l = 0; l < H; l += 2) {
            ww  = fmaf(Wout[v * H + l],     Wrp[l * H + tid],       ww);
            w1_ = fmaf(Wout[v * H + l + 1], Wrp[(l + 1) * H + tid], w1_);
        }
        g_Wcomb[v * H + tid] = ww + w1_;
    }
    if (tid == 0) {
        float bb = bout[v], bb1 = 0.f;
        #pragma unroll
        for (int l = 0; l < H; l += 2) {
            bb  = fmaf(Wout[v * H + l],     brp[l],     bb);
            bb1 = fmaf(Wout[v * H + l + 1], brp[l + 1], bb1);
        }
        g_bcomb[v] = bb + bb1;
    }

    // ---- barrier 1: all tables visible ----
    __syncthreads();
    if (tid == 0) {
        __threadfence();
        atomicAdd(&g_bar1, 1u);
        while (atomicAdd(&g_bar1, 0u) < 64u) { }
        __threadfence();
    }
    __syncthreads();

    // ================= Phase B: negated KK row v =================
    if (tid < H) {
        const int j = tid;
        const float4* kj4 = (const float4*)(g_ktab + j * H);
        const float4* ki4 = (const float4*)hs;
        float a0 = 0.f, a1 = 0.f, a2 = 0.f, a3 = 0.f;
        #pragma unroll
        for (int l = 0; l < 16; l++) {
            float4 ka = ki4[l], kb = __ldg(kj4 + l);
            a0 = fmaf(ka.x, kb.x, a0); a1 = fmaf(ka.y, kb.y, a1);
            a2 = fmaf(ka.z, kb.z, a2); a3 = fmaf(ka.w, kb.w, a3);
        }
        g_KKn[v * H + j] = -((a0 + a1) + (a2 + a3));
    }
    __syncthreads();
    if (tid == 0) { __threadfence(); atomicAdd(&g_bar2, 1u); }

    // ---- R-init: warp w computes batch v*4+w, hands off via smem ----
    {
        const unsigned char* myseq = sseq[w];
        const int qid = myseq[LL - 1];
        const float4* q4 = (const float4*)(g_qtab + qid * H);
        const float4* ka = (const float4*)(g_ktab + lo2 * H);
        const float4* kb = (const float4*)(g_ktab + (lo2 + 1) * H);
        float x0 = 0.f, x1 = 0.f, y0 = 0.f, y1 = 0.f;
        #pragma unroll
        for (int i = 0; i < 16; i += 2) {
            float4 q0 = __ldg(q4 + i),     a0 = __ldg(ka + i),     b0 = __ldg(kb + i);
            float4 q1 = __ldg(q4 + i + 1), a1 = __ldg(ka + i + 1), b1 = __ldg(kb + i + 1);
            x0 = fmaf(a0.x, q0.x, x0); x0 = fmaf(a0.y, q0.y, x0);
            x0 = fmaf(a0.z, q0.z, x0); x0 = fmaf(a0.w, q0.w, x0);
            x1 = fmaf(a1.x, q1.x, x1); x1 = fmaf(a1.y, q1.y, x1);
            x1 = fmaf(a1.z, q1.z, x1); x1 = fmaf(a1.w, q1.w, x1);
            y0 = fmaf(b0.x, q0.x, y0); y0 = fmaf(b0.y, q0.y, y0);
            y0 = fmaf(b0.z, q0.z, y0); y0 = fmaf(b0.w, q0.w, y0);
            y1 = fmaf(b1.x, q1.x, y1); y1 = fmaf(b1.y, q1.y, y1);
            y1 = fmaf(b1.z, q1.z, y1); y1 = fmaf(b1.w, q1.w, y1);
        }
        sRi[w][lo2]     = x0 + x1;
        sRi[w][lo2 + 1] = y0 + y1;
    }

    // ---- barrier 2 wait: all KK rows visible ----
    if (tid == 0) {
        while (atomicAdd(&g_bar2, 0u) < 64u) { }
        __threadfence();
    }
    __syncthreads();

    // ---- stage negated KK into smem ----
    {
        const float4* gg = (const float4*)g_KKn;
        float4* ks = (float4*)sKKn;
        #pragma unroll
        for (int i = tid; i < VOCAB * H / 4; i += 128) ks[i] = __ldg(gg + i);
    }
    __syncthreads();

    // ====== Phase C: warps 0-1 scan TWO batches each, interleaved ======
    if (w < 2) {
        const unsigned char* sqA = sseq[2 * w];
        const unsigned char* sqB = sseq[2 * w + 1];
        float RxA = sRi[2 * w][lo2],     RyA = sRi[2 * w][lo2 + 1];
        float RxB = sRi[2 * w + 1][lo2], RyB = sRi[2 * w + 1][lo2 + 1];
        float SxA = 0.f, SyA = 0.f, SxB = 0.f, SyB = 0.f;

        // 3 single steps: t = 2046, 2045, 2044
        #pragma unroll
        for (int t = LL - 2; t >= LL - 4; --t) {
            const int idA = (int)sqA[t];
            const int idB = (int)sqB[t];
            float tA = (idA & 1) ? RyA : RxA;
            float tB = (idB & 1) ? RyB : RxB;
            const float sA = __shfl_sync(FULL, tA, idA >> 1);
            const float sB = __shfl_sync(FULL, tB, idB >> 1);
            const float2 krA = *(const float2*)&sKKn[idA * H + lo2];
            const float2 krB = *(const float2*)&sKKn[idB * H + lo2];
            RxA = fmaf(krA.x, sA, RxA);  RyA = fmaf(krA.y, sA, RyA);
            RxB = fmaf(krB.x, sB, RxB);  RyB = fmaf(krB.y, sB, RyB);
            if (lane == (idA >> 1)) { if (idA & 1) SyA += sA; else SxA += sA; }
            if (lane == (idB >> 1)) { if (idB & 1) SyB += sB; else SxB += sB; }
        }

        // 511 groups of 4, two batches statically interleaved
        for (int base = LL - 8; base >= 0; base -= 4) {
            const unsigned int idsA = *(const unsigned int*)(sqA + base);
            const unsigned int idsB = *(const unsigned int*)(sqB + base);
            const int a0 = (int)(idsA >> 24), a1 = (int)((idsA >> 16) & 0xff);
            const int a2 = (int)((idsA >> 8) & 0xff), a3 = (int)(idsA & 0xff);
            const int b0 = (int)(idsB >> 24), b1 = (int)((idsB >> 16) & 0xff);
            const int b2 = (int)((idsB >> 8) & 0xff), b3 = (int)(idsB & 0xff);

            const int rA0 = a0 * H, rA1 = a1 * H, rA2 = a2 * H, rA3 = a3 * H;
            const int rB0 = b0 * H, rB1 = b1 * H, rB2 = b2 * H, rB3 = b3 * H;

            // negated Gram entries (12 LDS, independent)
            const float gA10 = sKKn[rA1 + a0];
            const float gA20 = sKKn[rA2 + a0], gA21 = sKKn[rA2 + a1];
            const float gA30 = sKKn[rA3 + a0], gA31 = sKKn[rA3 + a1], gA32 = sKKn[rA3 + a2];
            const float gB10 = sKKn[rB1 + b0];
            const float gB20 = sKKn[rB2 + b0], gB21 = sKKn[rB2 + b1];
            const float gB30 = sKKn[rB3 + b0], gB31 = sKKn[rB3 + b1], gB32 = sKKn[rB3 + b2];

            // update rows (independent of R)
            const float2 kA0 = *(const float2*)&sKKn[rA0 + lo2];
            const float2 kA1 = *(const float2*)&sKKn[rA1 + lo2];
            const float2 kA2 = *(const float2*)&sKKn[rA2 + lo2];
            const float2 kA3 = *(const float2*)&sKKn[rA3 + lo2];
            const float2 kB0 = *(const float2*)&sKKn[rB0 + lo2];
            const float2 kB1 = *(const float2*)&sKKn[rB1 + lo2];
            const float2 kB2 = *(const float2*)&sKKn[rB2 + lo2];
            const float2 kB3 = *(const float2*)&sKKn[rB3 + lo2];

            // d_j = R[id_j] via SEL + SHFL (A and B independent)
            float tA0 = (a0 & 1) ? RyA : RxA;
            float tA1 = (a1 & 1) ? RyA : RxA;
            float tA2 = (a2 & 1) ? RyA : RxA;
            float tA3 = (a3 & 1) ? RyA : RxA;
            float tB0 = (b0 & 1) ? RyB : RxB;
            float tB1 = (b1 & 1) ? RyB : RxB;
            float tB2 = (b2 & 1) ? RyB : RxB;
            float tB3 = (b3 & 1) ? RyB : RxB;
            const float dA0 = __shfl_sync(FULL, tA0, a0 >> 1);
            const float dB0 = __shfl_sync(FULL, tB0, b0 >> 1);
            const float dA1 = __shfl_sync(FULL, tA1, a1 >> 1);
            const float dB1 = __shfl_sync(FULL, tB1, b1 >> 1);
            const float dA2 = __shfl_sync(FULL, tA2, a2 >> 1);
            const float dB2 = __shfl_sync(FULL, tB2, b2 >> 1);
            const float dA3 = __shfl_sync(FULL, tA3, a3 >> 1);
            const float dB3 = __shfl_sync(FULL, tB3, b3 >> 1);

            // forward substitution (negated Gram -> pure FMA), interleaved
            const float sA0 = dA0;
            const float sB0 = dB0;
            const float sA1 = fmaf(gA10, sA0, dA1);
            const float sB1 = fmaf(gB10, sB0, dB1);
            const float sA2 = fmaf(gA21, sA1, fmaf(gA20, sA0, dA2));
            const float sB2 = fmaf(gB21, sB1, fmaf(gB20, sB0, dB2));
            const float sA3 = fmaf(gA32, sA2, fmaf(gA31, sA1, fmaf(gA30, sA0, dA3)));
            const float sB3 = fmaf(gB32, sB2, fmaf(gB31, sB1, fmaf(gB30, sB0, dB3)));

            // R += (-KK row_j) * s_j (pairwise trees)
            float dRxA = fmaf(kA1.x, sA1, kA0.x * sA0) + fmaf(kA3.x, sA3, kA2.x * sA2);
            float dRyA = fmaf(kA1.y, sA1, kA0.y * sA0) + fmaf(kA3.y, sA3, kA2.y * sA2);
            float dRxB = fmaf(kB1.x, sB1, kB0.x * sB0) + fmaf(kB3.x, sB3, kB2.x * sB2);
            float dRyB = fmaf(kB1.y, sB1, kB0.y * sB0) + fmaf(kB3.y, sB3, kB2.y * sB2);
            RxA += dRxA; RyA += dRyA;
            RxB += dRxB; RyB += dRyB;

            // per-vocab scatter: S[id_j] += s_j (owning lane only)
            if (lane == (a0 >> 1)) { if (a0 & 1) SyA += sA0; else SxA += sA0; }
            if (lane == (a1 >> 1)) { if (a1 & 1) SyA += sA1; else SxA += sA1; }
            if (lane == (a2 >> 1)) { if (a2 & 1) SyA += sA2; else SxA += sA2; }
            if (lane == (a3 >> 1)) { if (a3 & 1) SyA += sA3; else SxA += sA3; }
            if (lane == (b0 >> 1)) { if (b0 & 1) SyB += sB0; else SxB += sB0; }
            if (lane == (b1 >> 1)) { if (b1 & 1) SyB += sB1; else SxB += sB1; }
            if (lane == (b2 >> 1)) { if (b2 & 1) SyB += sB2; else SxB += sB2; }
            if (lane == (b3 >> 1)) { if (b3 & 1) SyB += sB3; else SxB += sB3; }
        }

        sS[2 * w][lo2]         = SxA;
        sS[2 * w][lo2 + 1]     = SyA;
        sS[2 * w + 1][lo2]     = SxB;
        sS[2 * w + 1][lo2 + 1] = SyB;
    }
    __syncthreads();

    // ---- epilogue: warp w handles batch v*4+w ----
    {
        float mx0 = 0.f, mx1 = 0.f, my0 = 0.f, my1 = 0.f;
        #pragma unroll 8
        for (int vv = 0; vv < VOCAB; vv += 2) {
            float sv0 = sS[w][vv], sv1 = sS[w][vv + 1];
            float2 vt0 = __ldg((const float2*)&g_vtab[vv * H + lo2]);
            float2 vt1 = __ldg((const float2*)&g_vtab[(vv + 1) * H + lo2]);
            mx0 = fmaf(sv0, vt0.x, mx0); my0 = fmaf(sv0, vt0.y, my0);
            mx1 = fmaf(sv1, vt1.x, mx1); my1 = fmaf(sv1, vt1.y, my1);
        }
        // reuse sRi as Mq scratch (done with R-init)
        sRi[w][lo2]     = mx0 + mx1;
        sRi[w][lo2 + 1] = my0 + my1;
    }
    __syncwarp();
    #pragma unroll
    for (int rr = 0; rr < 2; rr++) {
        const int i = lane + 32 * rr;
        const float4* w4 = (const float4*)(g_Wcomb + i * H);
        const float4* m4 = (const float4*)sRi[w];
        float a0 = 0.f, a1 = 0.f, a2 = 0.f, a3 = 0.f;
        #pragma unroll
        for (int j = 0; j < 16; j++) {
            float4 ww = __ldg(w4 + j);
            float4 m = m4[j];
            a0 = fmaf(ww.x, m.x, a0); a1 = fmaf(ww.y, m.y, a1);
            a2 = fmaf(ww.z, m.z, a2); a3 = fmaf(ww.w, m.w, a3);
        }
        out[(v * 4 + w) * H + i] = (a0 + a1) + (a2 + a3) + g_bcomb[i];
    }

    // ---- reset spin barriers for the next (graph-replayed) launch ----
    __syncthreads();
    if (tid == 0) {
        __threadfence();
        if (atomicAdd(&g_rst, 1u) == 63u) {
            atomicExch(&g_bar1, 0u);
            atomicExch(&g_bar2, 0u);
            atomicExch(&g_rst, 0u);
        }
    }
}

// ======================================================================
extern "C" void kernel_launch(void* const* d_in, const int* in_sizes, int n_in,
                              void* d_out, int out_size)
{
    (void)in_sizes; (void)n_in; (void)out_size;
    const int*   seq   = (const int*)  d_in[0];
    const float* embed = (const float*)d_in[1];
    const float* W1    = (const float*)d_in[2];
    const float* b1    = (const float*)d_in[3];
    const float* W2    = (const float*)d_in[4];
    const float* b2    = (const float*)d_in[5];
    const float* gamma = (const float*)d_in[6];
    const float* beta  = (const float*)d_in[7];
    const float* Wk    = (const float*)d_in[8];
    const float* Wv    = (const float*)d_in[9];
    const float* Wq    = (const float*)d_in[10];
    const float* Wrp   = (const float*)d_in[11];
    const float* brp   = (const float*)d_in[12];
    const float* Wout  = (const float*)d_in[13];
    const float* bout  = (const float*)d_in[14];

    fused_kernel<<<VOCAB, 128>>>(seq, embed, W1, b1, W2, b2, gamma, beta,
                                 Wk, Wv, Wq, Wrp, brp, Wout, bout,
                                 (float*)d_out);
}

// round 8
// speedup vs baseline: 1.1104x; 1.1104x over previous
#include <cuda_runtime.h>

#define H  64
#define LL 2048
#define VOCAB 64
#define NBLK 32
#define FULL 0xffffffffu

// -------- device-global scratch (no runtime allocation allowed) --------
__device__ __align__(16) float g_ktab[VOCAB * H];    // normalized k per vocab id
__device__ __align__(16) float g_vtab[VOCAB * H];    // v per vocab id
__device__ __align__(16) float g_qtab[VOCAB * H];    // q per vocab id
__device__ __align__(16) float g_KKn[VOCAB * VOCAB]; // NEGATED Gram of k table
__device__ __align__(16) float g_Wcomb[H * H];       // Wout @ Wrp
__device__ __align__(16) float g_bcomb[H];           // Wout @ brp + bout
__device__ unsigned g_bar1 = 0, g_bar2 = 0, g_rst = 0;   // spin barriers

__device__ __forceinline__ float bfly_sum(float v) {
    #pragma unroll
    for (int o = 16; o; o >>= 1) v += __shfl_xor_sync(FULL, v, o);
    return v;
}

// ======================================================================
// Single fused kernel. grid 32, block 256 (8 warps).
//   2 warps per SMSP -> dual-warp issue fills single-warp stall bubbles
//   (R6 scan was issue-bound at ~0.38 IPC with 1 warp/SMSP).
//   Phase A: two 128-thread halves encode vocab 2b and 2b+1. -> barrier 1
//   Phase B: negated KK rows 2b, 2b+1; 8 warps compute R-init for their
//            batches (hides barrier-2 wait).
//   Phase C: 8 warps scan 8 batches (proven R6 single-batch loop).
// ======================================================================
__global__ void __launch_bounds__(256) fused_kernel(
    const int*   __restrict__ seq,
    const float* __restrict__ embed, const float* __restrict__ W1,
    const float* __restrict__ b1, const float* __restrict__ W2,
    const float* __restrict__ b2, const float* __restrict__ gamma,
    const float* __restrict__ beta, const float* __restrict__ Wk,
    const float* __restrict__ Wv, const float* __restrict__ Wq,
    const float* __restrict__ Wrp, const float* __restrict__ brp,
    const float* __restrict__ Wout, const float* __restrict__ bout,
    float* __restrict__ out)
{
    __shared__ __align__(16) float sKKn[VOCAB * H];        // 16 KB
    __shared__ __align__(16) unsigned char sseq[8][LL];    // 16 KB
    __shared__ __align__(16) float e2[2][H], f12[2][2 * H];
    __shared__ __align__(16) float h2[2][H], hs2[2][H];
    __shared__ __align__(16) float sRi[8][H];              // R-init handoff
    __shared__ __align__(16) float sS[8][H];               // per-vocab s sums
    __shared__ float s_mu[2], s_rstd[2], s_kinv[2];

    const int tid  = threadIdx.x;
    const int lane = tid & 31;
    const int w    = tid >> 5;            // warp 0..7
    const int half = tid >> 7;            // 0 or 1
    const int t128 = tid & 127;           // tid within half
    const int v0   = blockIdx.x * 2 + half;   // vocab id this half encodes
    const int lo2  = 2 * lane;
    const int b    = blockIdx.x * 8 + w;  // batch this warp scans

    float* e  = e2[half];
    float* f1 = f12[half];
    float* h  = h2[half];
    float* hs = hs2[half];

    // ---- stage this block's 8 sequences (warp w -> batch b) ----
    {
        const int4* sg = (const int4*)(seq + b * LL);
        uchar4* ssh = (uchar4*)sseq[w];
        #pragma unroll 4
        for (int i = lane; i < LL / 4; i += 32) {
            int4 t = sg[i];
            ssh[i] = make_uchar4((unsigned char)t.x, (unsigned char)t.y,
                                 (unsigned char)t.z, (unsigned char)t.w);
        }
    }

    // ================= Phase A: encode vocab v0 (per half) =================
    if (t128 < H) e[t128] = embed[v0 * H + t128];
    __syncthreads();

    {   // ff1 = relu(W1 e + b1)  (128 threads per half)
        const float4* w4 = (const float4*)(W1 + t128 * H);
        const float4* e4 = (const float4*)e;
        float a0 = 0.f, a1 = 0.f, a2 = 0.f, a3 = 0.f;
        #pragma unroll
        for (int i = 0; i < 16; i++) {
            float4 ww = w4[i], ee = e4[i];
            a0 = fmaf(ww.x, ee.x, a0); a1 = fmaf(ww.y, ee.y, a1);
            a2 = fmaf(ww.z, ee.z, a2); a3 = fmaf(ww.w, ee.w, a3);
        }
        f1[t128] = fmaxf((a0 + a1) + (a2 + a3) + b1[t128], 0.0f);
    }
    __syncthreads();

    if (t128 < H) {   // h = e + W2 ff1 + b2
        const float4* w4 = (const float4*)(W2 + t128 * 2 * H);
        const float4* f4 = (const float4*)f1;
        float a0 = 0.f, a1 = 0.f, a2 = 0.f, a3 = 0.f;
        float b0 = 0.f, c1 = 0.f, c2 = 0.f, b3 = 0.f;
        #pragma unroll
        for (int i = 0; i < 32; i += 2) {
            float4 ww = w4[i], ff = f4[i];
            a0 = fmaf(ww.x, ff.x, a0); a1 = fmaf(ww.y, ff.y, a1);
            a2 = fmaf(ww.z, ff.z, a2); a3 = fmaf(ww.w, ff.w, a3);
            float4 w2_ = w4[i + 1], ff2 = f4[i + 1];
            b0 = fmaf(w2_.x, ff2.x, b0); c1 = fmaf(w2_.y, ff2.y, c1);
            c2 = fmaf(w2_.z, ff2.z, c2); b3 = fmaf(w2_.w, ff2.w, b3);
        }
        h[t128] = e[t128] + ((a0 + a1) + (a2 + a3)) + ((b0 + c1) + (c2 + b3)) + b2[t128];
    }
    __syncthreads();

    if (t128 < 32) {   // LayerNorm stats (biased var, eps 1e-5)
        float x = bfly_sum(h[t128] + h[t128 + 32]);
        float mu = x * (1.0f / H);
        float c0 = h[t128] - mu, c1_ = h[t128 + 32] - mu;
        float vv = bfly_sum(c0 * c0 + c1_ * c1_);
        if (t128 == 0) { s_mu[half] = mu; s_rstd[half] = rsqrtf(vv * (1.0f / H) + 1e-5f); }
    }
    __syncthreads();
    if (t128 < H) hs[t128] = (h[t128] - s_mu[half]) * s_rstd[half] * gamma[t128] + beta[t128];
    __syncthreads();

    if (t128 < H) {   // k (raw) and q projections
        const float4* wk4 = (const float4*)(Wk + t128 * H);
        const float4* wq4 = (const float4*)(Wq + t128 * H);
        const float4* h4 = (const float4*)hs;
        float k0 = 0.f, k1 = 0.f, k2 = 0.f, k3 = 0.f;
        float q0 = 0.f, q1 = 0.f, q2 = 0.f, q3 = 0.f;
        #pragma unroll
        for (int i = 0; i < 16; i++) {
            float4 wk = wk4[i], wq = wq4[i], hh = h4[i];
            k0 = fmaf(wk.x, hh.x, k0); k1 = fmaf(wk.y, hh.y, k1);
            k2 = fmaf(wk.z, hh.z, k2); k3 = fmaf(wk.w, hh.w, k3);
            q0 = fmaf(wq.x, hh.x, q0); q1 = fmaf(wq.y, hh.y, q1);
            q2 = fmaf(wq.z, hh.z, q2); q3 = fmaf(wq.w, hh.w, q3);
        }
        h[t128] = (k0 + k1) + (k2 + k3);
        g_qtab[v0 * H + t128] = (q0 + q1) + (q2 + q3);
    } else {         // v projection
        const int i = t128 - H;
        const float4* wv4 = (const float4*)(Wv + i * H);
        const float4* h4 = (const float4*)hs;
        float a0 = 0.f, a1 = 0.f, a2 = 0.f, a3 = 0.f;
        #pragma unroll
        for (int j = 0; j < 16; j++) {
            float4 ww = wv4[j], hh = h4[j];
            a0 = fmaf(ww.x, hh.x, a0); a1 = fmaf(ww.y, hh.y, a1);
            a2 = fmaf(ww.z, hh.z, a2); a3 = fmaf(ww.w, hh.w, a3);
        }
        g_vtab[v0 * H + i] = (a0 + a1) + (a2 + a3);
    }
    __syncthreads();

    if (t128 < 32) {   // k normalization
        float n = bfly_sum(h[t128] * h[t128] + h[t128 + 32] * h[t128 + 32]);
        if (t128 == 0) s_kinv[half] = 1.0f / fmaxf(sqrtf(n), 1e-12f);
    }
    __syncthreads();
    if (t128 < H) {
        float kv = h[t128] * s_kinv[half];
        g_ktab[v0 * H + t128] = kv;
        hs[t128] = kv;                 // own k row for KK phase
    }

    // Wcomb row v0 + bcomb[v0]
    if (t128 < H) {
        float ww = 0.f, w1_ = 0.f;
        #pragma unroll
        for (int l = 0; l < H; l += 2) {
            ww  = fmaf(Wout[v0 * H + l],     Wrp[l * H + t128],       ww);
            w1_ = fmaf(Wout[v0 * H + l + 1], Wrp[(l + 1) * H + t128], w1_);
        }
        g_Wcomb[v0 * H + t128] = ww + w1_;
    }
    if (t128 == 0) {
        float bb = bout[v0], bb1 = 0.f;
        #pragma unroll
        for (int l = 0; l < H; l += 2) {
            bb  = fmaf(Wout[v0 * H + l],     brp[l],     bb);
            bb1 = fmaf(Wout[v0 * H + l + 1], brp[l + 1], bb1);
        }
        g_bcomb[v0] = bb + bb1;
    }

    // ---- barrier 1: all tables visible ----
    __syncthreads();
    if (tid == 0) {
        __threadfence();
        atomicAdd(&g_bar1, 1u);
        while (atomicAdd(&g_bar1, 0u) < (unsigned)NBLK) { }
        __threadfence();
    }
    __syncthreads();

    // ================= Phase B: negated KK row v0 (per half) =================
    if (t128 < H) {
        const int j = t128;
        const float4* kj4 = (const float4*)(g_ktab + j * H);
        const float4* ki4 = (const float4*)hs;
        float a0 = 0.f, a1 = 0.f, a2 = 0.f, a3 = 0.f;
        #pragma unroll
        for (int l = 0; l < 16; l++) {
            float4 ka = ki4[l], kb = __ldg(kj4 + l);
            a0 = fmaf(ka.x, kb.x, a0); a1 = fmaf(ka.y, kb.y, a1);
            a2 = fmaf(ka.z, kb.z, a2); a3 = fmaf(ka.w, kb.w, a3);
        }
        g_KKn[v0 * H + j] = -((a0 + a1) + (a2 + a3));
    }
    __syncthreads();
    if (tid == 0) { __threadfence(); atomicAdd(&g_bar2, 1u); }

    // ---- R-init: warp w computes batch b, hands off via smem ----
    {
        const unsigned char* myseq = sseq[w];
        const int qid = myseq[LL - 1];
        const float4* q4 = (const float4*)(g_qtab + qid * H);
        const float4* ka = (const float4*)(g_ktab + lo2 * H);
        const float4* kb = (const float4*)(g_ktab + (lo2 + 1) * H);
        float x0 = 0.f, x1 = 0.f, y0 = 0.f, y1 = 0.f;
        #pragma unroll
        for (int i = 0; i < 16; i += 2) {
            float4 q0 = __ldg(q4 + i),     a0 = __ldg(ka + i),     b0 = __ldg(kb + i);
            float4 q1 = __ldg(q4 + i + 1), a1 = __ldg(ka + i + 1), b1 = __ldg(kb + i + 1);
            x0 = fmaf(a0.x, q0.x, x0); x0 = fmaf(a0.y, q0.y, x0);
            x0 = fmaf(a0.z, q0.z, x0); x0 = fmaf(a0.w, q0.w, x0);
            x1 = fmaf(a1.x, q1.x, x1); x1 = fmaf(a1.y, q1.y, x1);
            x1 = fmaf(a1.z, q1.z, x1); x1 = fmaf(a1.w, q1.w, x1);
            y0 = fmaf(b0.x, q0.x, y0); y0 = fmaf(b0.y, q0.y, y0);
            y0 = fmaf(b0.z, q0.z, y0); y0 = fmaf(b0.w, q0.w, y0);
            y1 = fmaf(b1.x, q1.x, y1); y1 = fmaf(b1.y, q1.y, y1);
            y1 = fmaf(b1.z, q1.z, y1); y1 = fmaf(b1.w, q1.w, y1);
        }
        sRi[w][lo2]     = x0 + x1;
        sRi[w][lo2 + 1] = y0 + y1;
    }

    // ---- barrier 2 wait: all KK rows visible ----
    if (tid == 0) {
        while (atomicAdd(&g_bar2, 0u) < (unsigned)NBLK) { }
        __threadfence();
    }
    __syncthreads();

    // ---- stage negated KK into smem ----
    {
        const float4* gg = (const float4*)g_KKn;
        float4* ks = (float4*)sKKn;
        #pragma unroll
        for (int i = tid; i < VOCAB * H / 4; i += 256) ks[i] = __ldg(gg + i);
    }
    __syncthreads();

    // ====== Phase C: 8 warps scan 8 batches (2 warps per SMSP) ======
    {
        const unsigned char* myseq = sseq[w];
        float Rx = sRi[w][lo2], Ry = sRi[w][lo2 + 1];
        float Sx = 0.f, Sy = 0.f;

        // 3 single steps: t = 2046, 2045, 2044
        #pragma unroll
        for (int t = LL - 2; t >= LL - 4; --t) {
            const int id = (int)myseq[t];
            float tmp = (id & 1) ? Ry : Rx;
            float s = __shfl_sync(FULL, tmp, id >> 1);
            const float2 kr = *(const float2*)&sKKn[id * H + lo2];
            Rx = fmaf(kr.x, s, Rx);  Ry = fmaf(kr.y, s, Ry);
            if (lane == (id >> 1)) { if (id & 1) Sy += s; else Sx += s; }
        }

        // 511 groups of 4
        #pragma unroll 2
        for (int base = LL - 8; base >= 0; base -= 4) {
            const unsigned int ids = *(const unsigned int*)(myseq + base);
            const int id0 = (int)(ids >> 24);          // t = base+3 (largest)
            const int id1 = (int)((ids >> 16) & 0xff);
            const int id2 = (int)((ids >> 8) & 0xff);
            const int id3 = (int)(ids & 0xff);

            const int r0 = id0 * H, r1 = id1 * H, r2 = id2 * H, r3 = id3 * H;

            // negated Gram entries
            const float gn10 = sKKn[r1 + id0];
            const float gn20 = sKKn[r2 + id0];
            const float gn21 = sKKn[r2 + id1];
            const float gn30 = sKKn[r3 + id0];
            const float gn31 = sKKn[r3 + id1];
            const float gn32 = sKKn[r3 + id2];

            // update rows (independent of R; issued early)
            const float2 k0 = *(const float2*)&sKKn[r0 + lo2];
            const float2 k1 = *(const float2*)&sKKn[r1 + lo2];
            const float2 k2 = *(const float2*)&sKKn[r2 + lo2];
            const float2 k3 = *(const float2*)&sKKn[r3 + lo2];

            // d_j = R[id_j] via SEL + SHFL
            float t0 = (id0 & 1) ? Ry : Rx;
            float t1 = (id1 & 1) ? Ry : Rx;
            float t2 = (id2 & 1) ? Ry : Rx;
            float t3 = (id3 & 1) ? Ry : Rx;
            const float d0 = __shfl_sync(FULL, t0, id0 >> 1);
            const float d1 = __shfl_sync(FULL, t1, id1 >> 1);
            const float d2 = __shfl_sync(FULL, t2, id2 >> 1);
            const float d3 = __shfl_sync(FULL, t3, id3 >> 1);

            // forward substitution (negated Gram -> pure FMA)
            const float s0 = d0;
            const float s1 = fmaf(gn10, s0, d1);
            const float s2 = fmaf(gn21, s1, fmaf(gn20, s0, d2));
            const float s3 = fmaf(gn32, s2, fmaf(gn31, s1, fmaf(gn30, s0, d3)));

            // R += (-KK row_j) * s_j (pairwise tree)
            float dRx = fmaf(k1.x, s1, k0.x * s0) + fmaf(k3.x, s3, k2.x * s2);
            float dRy = fmaf(k1.y, s1, k0.y * s0) + fmaf(k3.y, s3, k2.y * s2);
            Rx += dRx; Ry += dRy;

            // per-vocab scatter: S[id_j] += s_j (owning lane only)
            if (lane == (id0 >> 1)) { if (id0 & 1) Sy += s0; else Sx += s0; }
            if (lane == (id1 >> 1)) { if (id1 & 1) Sy += s1; else Sx += s1; }
            if (lane == (id2 >> 1)) { if (id2 & 1) Sy += s2; else Sx += s2; }
            if (lane == (id3 >> 1)) { if (id3 & 1) Sy += s3; else Sx += s3; }
        }

        sS[w][lo2]     = Sx;
        sS[w][lo2 + 1] = Sy;
    }
    __syncwarp();

    // ---- Mq = sum_v S_v * vtab[v], then out = Wcomb @ Mq + bcomb ----
    {
        float mx0 = 0.f, mx1 = 0.f, my0 = 0.f, my1 = 0.f;
        #pragma unroll 8
        for (int vv = 0; vv < VOCAB; vv += 2) {
            float sv0 = sS[w][vv], sv1 = sS[w][vv + 1];
            float2 vt0 = __ldg((const float2*)&g_vtab[vv * H + lo2]);
            float2 vt1 = __ldg((const float2*)&g_vtab[(vv + 1) * H + lo2]);
            mx0 = fmaf(sv0, vt0.x, mx0); my0 = fmaf(sv0, vt0.y, my0);
            mx1 = fmaf(sv1, vt1.x, mx1); my1 = fmaf(sv1, vt1.y, my1);
        }
        // reuse sRi as Mq scratch (done with R-init)
        sRi[w][lo2]     = mx0 + mx1;
        sRi[w][lo2 + 1] = my0 + my1;
    }
    __syncwarp();
    #pragma unroll
    for (int rr = 0; rr < 2; rr++) {
        const int i = lane + 32 * rr;
        const float4* w4 = (const float4*)(g_Wcomb + i * H);
        const float4* m4 = (const float4*)sRi[w];
        float a0 = 0.f, a1 = 0.f, a2 = 0.f, a3 = 0.f;
        #pragma unroll
        for (int j = 0; j < 16; j++) {
            float4 ww = __ldg(w4 + j);
            float4 m = m4[j];
            a0 = fmaf(ww.x, m.x, a0); a1 = fmaf(ww.y, m.y, a1);
            a2 = fmaf(ww.z, m.z, a2); a3 = fmaf(ww.w, m.w, a3);
        }
        out[b * H + i] = (a0 + a1) + (a2 + a3) + g_bcomb[i];
    }

    // ---- reset spin barriers for the next (graph-replayed) launch ----
    __syncthreads();
    if (tid == 0) {
        __threadfence();
        if (atomicAdd(&g_rst, 1u) == (unsigned)(NBLK - 1)) {
            atomicExch(&g_bar1, 0u);
            atomicExch(&g_bar2, 0u);
            atomicExch(&g_rst, 0u);
        }
    }
}

// ======================================================================
extern "C" void kernel_launch(void* const* d_in, const int* in_sizes, int n_in,
                              void* d_out, int out_size)
{
    (void)in_sizes; (void)n_in; (void)out_size;
    const int*   seq   = (const int*)  d_in[0];
    const float* embed = (const float*)d_in[1];
    const float* W1    = (const float*)d_in[2];
    const float* b1    = (const float*)d_in[3];
    const float* W2    = (const float*)d_in[4];
    const float* b2    = (const float*)d_in[5];
    const float* gamma = (const float*)d_in[6];
    const float* beta  = (const float*)d_in[7];
    const float* Wk    = (const float*)d_in[8];
    const float* Wv    = (const float*)d_in[9];
    const float* Wq    = (const float*)d_in[10];
    const float* Wrp   = (const float*)d_in[11];
    const float* brp   = (const float*)d_in[12];
    const float* Wout  = (const float*)d_in[13];
    const float* bout  = (const float*)d_in[14];

    fused_kernel<<<NBLK, 256>>>(seq, embed, W1, b1, W2, b2, gamma, beta,
                                Wk, Wv, Wq, Wrp, brp, Wout, bout,
                                (float*)d_out);
}

// round 9
// speedup vs baseline: 1.5155x; 1.3648x over previous
#include <cuda_runtime.h>

#define H  64
#define LL 2048
#define VOCAB 64
#define NBLK 64
#define FULL 0xffffffffu

// -------- device-global scratch (no runtime allocation allowed) --------
__device__ __align__(16) float g_ktab[VOCAB * H];    // normalized k per vocab id
__device__ __align__(16) float g_vtab[VOCAB * H];    // v per vocab id
__device__ __align__(16) float g_qtab[VOCAB * H];    // q per vocab id
__device__ __align__(16) float g_KKn[VOCAB * VOCAB]; // NEGATED Gram of k table
__device__ __align__(16) float g_Wcomb[H * H];       // Wout @ Wrp
__device__ __align__(16) float g_bcomb[H];           // Wout @ brp + bout
__device__ unsigned g_bar1 = 0, g_bar2 = 0, g_rst = 0;   // spin barriers

__device__ __forceinline__ float bfly_sum(float v) {
    #pragma unroll
    for (int o = 16; o; o >>= 1) v += __shfl_xor_sync(FULL, v, o);
    return v;
}

// ======================================================================
// Single fused kernel. grid 64, block 128 (R6 layout: 1 warp/SMSP).
// Phase C reworked to C=8 chunks: wall time is the per-warp serial chain,
// so amortize SHFL latency over 8 steps (8 independent SHFLs pipeline)
// and batch the substitution (28 FMA, depth 7).
// ======================================================================
__global__ void __launch_bounds__(128) fused_kernel(
    const int*   __restrict__ seq,
    const float* __restrict__ embed, const float* __restrict__ W1,
    const float* __restrict__ b1, const float* __restrict__ W2,
    const float* __restrict__ b2, const float* __restrict__ gamma,
    const float* __restrict__ beta, const float* __restrict__ Wk,
    const float* __restrict__ Wv, const float* __restrict__ Wq,
    const float* __restrict__ Wrp, const float* __restrict__ brp,
    const float* __restrict__ Wout, const float* __restrict__ bout,
    float* __restrict__ out)
{
    __shared__ __align__(16) float sKKn[VOCAB * H];        // 16 KB
    __shared__ __align__(16) unsigned char sseq[4][LL];    // 8 KB
    __shared__ __align__(16) float e[H], f1[2 * H], h[H], hs[H];
    __shared__ __align__(16) float sRi[4][H];              // R-init handoff
    __shared__ __align__(16) float sS[4][H];               // per-vocab s sums
    __shared__ float s_mu, s_rstd, s_kinv;

    const int v    = blockIdx.x;
    const int tid  = threadIdx.x;
    const int lane = tid & 31;
    const int w    = tid >> 5;
    const int lo2  = 2 * lane;
    const int b    = v * 4 + w;

    // ---- stage this block's 4 sequences (warp w stages batch b) ----
    {
        const int4* sg = (const int4*)(seq + b * LL);
        uchar4* ssh = (uchar4*)sseq[w];
        #pragma unroll 4
        for (int i = lane; i < LL / 4; i += 32) {
            int4 t = sg[i];
            ssh[i] = make_uchar4((unsigned char)t.x, (unsigned char)t.y,
                                 (unsigned char)t.z, (unsigned char)t.w);
        }
    }

    // ================= Phase A: encode vocab v =================
    if (tid < H) e[tid] = embed[v * H + tid];
    __syncthreads();

    {   // ff1 = relu(W1 e + b1)
        const float4* w4 = (const float4*)(W1 + tid * H);
        const float4* e4 = (const float4*)e;
        float a0 = 0.f, a1 = 0.f, a2 = 0.f, a3 = 0.f;
        #pragma unroll
        for (int i = 0; i < 16; i++) {
            float4 ww = w4[i], ee = e4[i];
            a0 = fmaf(ww.x, ee.x, a0); a1 = fmaf(ww.y, ee.y, a1);
            a2 = fmaf(ww.z, ee.z, a2); a3 = fmaf(ww.w, ee.w, a3);
        }
        f1[tid] = fmaxf((a0 + a1) + (a2 + a3) + b1[tid], 0.0f);
    }
    __syncthreads();

    if (tid < H) {   // h = e + W2 ff1 + b2
        const float4* w4 = (const float4*)(W2 + tid * 2 * H);
        const float4* f4 = (const float4*)f1;
        float a0 = 0.f, a1 = 0.f, a2 = 0.f, a3 = 0.f;
        float b0 = 0.f, c1 = 0.f, c2 = 0.f, b3 = 0.f;
        #pragma unroll
        for (int i = 0; i < 32; i += 2) {
            float4 ww = w4[i], ff = f4[i];
            a0 = fmaf(ww.x, ff.x, a0); a1 = fmaf(ww.y, ff.y, a1);
            a2 = fmaf(ww.z, ff.z, a2); a3 = fmaf(ww.w, ff.w, a3);
            float4 w2_ = w4[i + 1], ff2 = f4[i + 1];
            b0 = fmaf(w2_.x, ff2.x, b0); c1 = fmaf(w2_.y, ff2.y, c1);
            c2 = fmaf(w2_.z, ff2.z, c2); b3 = fmaf(w2_.w, ff2.w, b3);
        }
        h[tid] = e[tid] + ((a0 + a1) + (a2 + a3)) + ((b0 + c1) + (c2 + b3)) + b2[tid];
    }
    __syncthreads();

    if (tid < 32) {   // LayerNorm stats (biased var, eps 1e-5)
        float x = bfly_sum(h[tid] + h[tid + 32]);
        float mu = x * (1.0f / H);
        float c0 = h[tid] - mu, c1_ = h[tid + 32] - mu;
        float vv = bfly_sum(c0 * c0 + c1_ * c1_);
        if (tid == 0) { s_mu = mu; s_rstd = rsqrtf(vv * (1.0f / H) + 1e-5f); }
    }
    __syncthreads();
    if (tid < H) hs[tid] = (h[tid] - s_mu) * s_rstd * gamma[tid] + beta[tid];
    __syncthreads();

    if (tid < H) {   // k (raw) and q projections
        const float4* wk4 = (const float4*)(Wk + tid * H);
        const float4* wq4 = (const float4*)(Wq + tid * H);
        const float4* h4 = (const float4*)hs;
        float k0 = 0.f, k1 = 0.f, k2 = 0.f, k3 = 0.f;
        float q0 = 0.f, q1 = 0.f, q2 = 0.f, q3 = 0.f;
        #pragma unroll
        for (int i = 0; i < 16; i++) {
            float4 wk = wk4[i], wq = wq4[i], hh = h4[i];
            k0 = fmaf(wk.x, hh.x, k0); k1 = fmaf(wk.y, hh.y, k1);
            k2 = fmaf(wk.z, hh.z, k2); k3 = fmaf(wk.w, hh.w, k3);
            q0 = fmaf(wq.x, hh.x, q0); q1 = fmaf(wq.y, hh.y, q1);
            q2 = fmaf(wq.z, hh.z, q2); q3 = fmaf(wq.w, hh.w, q3);
        }
        h[tid] = (k0 + k1) + (k2 + k3);
        g_qtab[v * H + tid] = (q0 + q1) + (q2 + q3);
    } else {         // v projection
        const int i = tid - H;
        const float4* wv4 = (const float4*)(Wv + i * H);
        const float4* h4 = (const float4*)hs;
        float a0 = 0.f, a1 = 0.f, a2 = 0.f, a3 = 0.f;
        #pragma unroll
        for (int j = 0; j < 16; j++) {
            float4 ww = wv4[j], hh = h4[j];
            a0 = fmaf(ww.x, hh.x, a0); a1 = fmaf(ww.y, hh.y, a1);
            a2 = fmaf(ww.z, hh.z, a2); a3 = fmaf(ww.w, hh.w, a3);
        }
        g_vtab[v * H + i] = (a0 + a1) + (a2 + a3);
    }
    __syncthreads();

    if (tid < 32) {   // k normalization
        float n = bfly_sum(h[tid] * h[tid] + h[tid + 32] * h[tid + 32]);
        if (tid == 0) s_kinv = 1.0f / fmaxf(sqrtf(n), 1e-12f);
    }
    __syncthreads();
    if (tid < H) {
        float kv = h[tid] * s_kinv;
        g_ktab[v * H + tid] = kv;
        hs[tid] = kv;                 // keep own k row in smem for KK phase
    }

    // Wcomb row v + bcomb[v]
    if (tid < H) {
        float ww = 0.f, w1_ = 0.f;
        #pragma unroll
        for (int l = 0; l < H; l += 2) {
            ww  = fmaf(Wout[v * H + l],     Wrp[l * H + tid],       ww);
            w1_ = fmaf(Wout[v * H + l + 1], Wrp[(l + 1) * H + tid], w1_);
        }
        g_Wcomb[v * H + tid] = ww + w1_;
    }
    if (tid == 0) {
        float bb = bout[v], bb1 = 0.f;
        #pragma unroll
        for (int l = 0; l < H; l += 2) {
            bb  = fmaf(Wout[v * H + l],     brp[l],     bb);
            bb1 = fmaf(Wout[v * H + l + 1], brp[l + 1], bb1);
        }
        g_bcomb[v] = bb + bb1;
    }

    // ---- barrier 1: all tables visible ----
    __syncthreads();
    if (tid == 0) {
        __threadfence();
        atomicAdd(&g_bar1, 1u);
        while (atomicAdd(&g_bar1, 0u) < (unsigned)NBLK) { }
        __threadfence();
    }
    __syncthreads();

    // ================= Phase B: negated KK row v =================
    if (tid < H) {
        const int j = tid;
        const float4* kj4 = (const float4*)(g_ktab + j * H);
        const float4* ki4 = (const float4*)hs;
        float a0 = 0.f, a1 = 0.f, a2 = 0.f, a3 = 0.f;
        #pragma unroll
        for (int l = 0; l < 16; l++) {
            float4 ka = ki4[l], kb = __ldg(kj4 + l);
            a0 = fmaf(ka.x, kb.x, a0); a1 = fmaf(ka.y, kb.y, a1);
            a2 = fmaf(ka.z, kb.z, a2); a3 = fmaf(ka.w, kb.w, a3);
        }
        g_KKn[v * H + j] = -((a0 + a1) + (a2 + a3));
    }
    __syncthreads();
    if (tid == 0) { __threadfence(); atomicAdd(&g_bar2, 1u); }

    // ---- R-init: warp w computes batch b, hands off via smem ----
    {
        const unsigned char* myseq = sseq[w];
        const int qid = myseq[LL - 1];
        const float4* q4 = (const float4*)(g_qtab + qid * H);
        const float4* ka = (const float4*)(g_ktab + lo2 * H);
        const float4* kb = (const float4*)(g_ktab + (lo2 + 1) * H);
        float x0 = 0.f, x1 = 0.f, y0 = 0.f, y1 = 0.f;
        #pragma unroll
        for (int i = 0; i < 16; i += 2) {
            float4 q0 = __ldg(q4 + i),     a0 = __ldg(ka + i),     b0 = __ldg(kb + i);
            float4 q1 = __ldg(q4 + i + 1), a1 = __ldg(ka + i + 1), b1 = __ldg(kb + i + 1);
            x0 = fmaf(a0.x, q0.x, x0); x0 = fmaf(a0.y, q0.y, x0);
            x0 = fmaf(a0.z, q0.z, x0); x0 = fmaf(a0.w, q0.w, x0);
            x1 = fmaf(a1.x, q1.x, x1); x1 = fmaf(a1.y, q1.y, x1);
            x1 = fmaf(a1.z, q1.z, x1); x1 = fmaf(a1.w, q1.w, x1);
            y0 = fmaf(b0.x, q0.x, y0); y0 = fmaf(b0.y, q0.y, y0);
            y0 = fmaf(b0.z, q0.z, y0); y0 = fmaf(b0.w, q0.w, y0);
            y1 = fmaf(b1.x, q1.x, y1); y1 = fmaf(b1.y, q1.y, y1);
            y1 = fmaf(b1.z, q1.z, y1); y1 = fmaf(b1.w, q1.w, y1);
        }
        sRi[w][lo2]     = x0 + x1;
        sRi[w][lo2 + 1] = y0 + y1;
    }

    // ---- barrier 2 wait: all KK rows visible ----
    if (tid == 0) {
        while (atomicAdd(&g_bar2, 0u) < (unsigned)NBLK) { }
        __threadfence();
    }
    __syncthreads();

    // ---- stage negated KK into smem ----
    {
        const float4* gg = (const float4*)g_KKn;
        float4* ks = (float4*)sKKn;
        #pragma unroll
        for (int i = tid; i < VOCAB * H / 4; i += 128) ks[i] = __ldg(gg + i);
    }
    __syncthreads();

    // ====== Phase C: one warp per batch, C=8 chunks ======
    {
        const unsigned char* myseq = sseq[w];
        float Rx = sRi[w][lo2], Ry = sRi[w][lo2 + 1];
        float Sx = 0.f, Sy = 0.f;

        // 7 single steps: t = 2046 .. 2040
        #pragma unroll
        for (int t = LL - 2; t >= LL - 8; --t) {
            const int id = (int)myseq[t];
            float tmp = (id & 1) ? Ry : Rx;
            float s = __shfl_sync(FULL, tmp, id >> 1);
            const float2 kr = *(const float2*)&sKKn[id * H + lo2];
            Rx = fmaf(kr.x, s, Rx);  Ry = fmaf(kr.y, s, Ry);
            if (lane == (id >> 1)) { if (id & 1) Sy += s; else Sx += s; }
        }

        // 255 groups of 8: t in [base, base+7], j=0 is largest t
        #pragma unroll 1
        for (int base = LL - 16; base >= 0; base -= 8) {
            const uint2 u = *(const uint2*)(myseq + base);
            const int id7 = (int)(u.x & 0xff),         id6 = (int)((u.x >> 8) & 0xff);
            const int id5 = (int)((u.x >> 16) & 0xff), id4 = (int)(u.x >> 24);
            const int id3 = (int)(u.y & 0xff),         id2 = (int)((u.y >> 8) & 0xff);
            const int id1 = (int)((u.y >> 16) & 0xff), id0 = (int)(u.y >> 24);

            const int r0 = id0 * H, r1 = id1 * H, r2 = id2 * H, r3 = id3 * H;
            const int r4 = id4 * H, r5 = id5 * H, r6 = id6 * H, r7 = id7 * H;

            // 28 negated Gram entries (id-dependent only; hoistable)
            const float g10 = sKKn[r1 + id0];
            const float g20 = sKKn[r2 + id0], g21 = sKKn[r2 + id1];
            const float g30 = sKKn[r3 + id0], g31 = sKKn[r3 + id1], g32 = sKKn[r3 + id2];
            const float g40 = sKKn[r4 + id0], g41 = sKKn[r4 + id1], g42 = sKKn[r4 + id2], g43 = sKKn[r4 + id3];
            const float g50 = sKKn[r5 + id0], g51 = sKKn[r5 + id1], g52 = sKKn[r5 + id2], g53 = sKKn[r5 + id3], g54 = sKKn[r5 + id4];
            const float g60 = sKKn[r6 + id0], g61 = sKKn[r6 + id1], g62 = sKKn[r6 + id2], g63 = sKKn[r6 + id3], g64 = sKKn[r6 + id4], g65 = sKKn[r6 + id5];
            const float g70 = sKKn[r7 + id0], g71 = sKKn[r7 + id1], g72 = sKKn[r7 + id2], g73 = sKKn[r7 + id3], g74 = sKKn[r7 + id4], g75 = sKKn[r7 + id5], g76 = sKKn[r7 + id6];

            // 8 update rows (id-dependent only)
            const float2 k0 = *(const float2*)&sKKn[r0 + lo2];
            const float2 k1 = *(const float2*)&sKKn[r1 + lo2];
            const float2 k2 = *(const float2*)&sKKn[r2 + lo2];
            const float2 k3 = *(const float2*)&sKKn[r3 + lo2];
            const float2 k4 = *(const float2*)&sKKn[r4 + lo2];
            const float2 k5 = *(const float2*)&sKKn[r5 + lo2];
            const float2 k6 = *(const float2*)&sKKn[r6 + lo2];
            const float2 k7 = *(const float2*)&sKKn[r7 + lo2];

            // 8 independent gathers d_j = R[id_j] — pipelined SHFLs
            float t0 = (id0 & 1) ? Ry : Rx;
            float t1 = (id1 & 1) ? Ry : Rx;
            float t2 = (id2 & 1) ? Ry : Rx;
            float t3 = (id3 & 1) ? Ry : Rx;
            float t4 = (id4 & 1) ? Ry : Rx;
            float t5 = (id5 & 1) ? Ry : Rx;
            float t6 = (id6 & 1) ? Ry : Rx;
            float t7 = (id7 & 1) ? Ry : Rx;
            const float d0 = __shfl_sync(FULL, t0, id0 >> 1);
            const float d1 = __shfl_sync(FULL, t1, id1 >> 1);
            const float d2 = __shfl_sync(FULL, t2, id2 >> 1);
            const float d3 = __shfl_sync(FULL, t3, id3 >> 1);
            const float d4 = __shfl_sync(FULL, t4, id4 >> 1);
            const float d5 = __shfl_sync(FULL, t5, id5 >> 1);
            const float d6 = __shfl_sync(FULL, t6, id6 >> 1);
            const float d7 = __shfl_sync(FULL, t7, id7 >> 1);

            // forward substitution with negated Gram: s_j = d_j + sum g_jm s_m
            const float s0 = d0;
            const float s1 = fmaf(g10, s0, d1);
            const float s2 = fmaf(g21, s1, fmaf(g20, s0, d2));
            const float s3 = fmaf(g32, s2, fmaf(g31, s1, fmaf(g30, s0, d3)));
            const float s4 = fmaf(g43, s3, fmaf(g42, s2, fmaf(g41, s1, fmaf(g40, s0, d4))));
            const float s5 = fmaf(g54, s4, fmaf(g53, s3, fmaf(g52, s2, fmaf(g51, s1, fmaf(g50, s0, d5)))));
            const float s6 = fmaf(g65, s5, fmaf(g64, s4, fmaf(g63, s3, fmaf(g62, s2, fmaf(g61, s1, fmaf(g60, s0, d6))))));
            const float s7 = fmaf(g76, s6, fmaf(g75, s5, fmaf(g74, s4, fmaf(g73, s3, fmaf(g72, s2, fmaf(g71, s1, fmaf(g70, s0, d7)))))));

            // R += sum_j (-KK row_j) * s_j  (pairwise tree, depth 4)
            float px0 = fmaf(k1.x, s1, k0.x * s0);
            float px1 = fmaf(k3.x, s3, k2.x * s2);
            float px2 = fmaf(k5.x, s5, k4.x * s4);
            float px3 = fmaf(k7.x, s7, k6.x * s6);
            float py0 = fmaf(k1.y, s1, k0.y * s0);
            float py1 = fmaf(k3.y, s3, k2.y * s2);
            float py2 = fmaf(k5.y, s5, k4.y * s4);
            float py3 = fmaf(k7.y, s7, k6.y * s6);
            Rx += (px0 + px1) + (px2 + px3);
            Ry += (py0 + py1) + (py2 + py3);

            // per-vocab scatter: S[id_j] += s_j (owning lane only)
            if (lane == (id0 >> 1)) { if (id0 & 1) Sy += s0; else Sx += s0; }
            if (lane == (id1 >> 1)) { if (id1 & 1) Sy += s1; else Sx += s1; }
            if (lane == (id2 >> 1)) { if (id2 & 1) Sy += s2; else Sx += s2; }
            if (lane == (id3 >> 1)) { if (id3 & 1) Sy += s3; else Sx += s3; }
            if (lane == (id4 >> 1)) { if (id4 & 1) Sy += s4; else Sx += s4; }
            if (lane == (id5 >> 1)) { if (id5 & 1) Sy += s5; else Sx += s5; }
            if (lane == (id6 >> 1)) { if (id6 & 1) Sy += s6; else Sx += s6; }
            if (lane == (id7 >> 1)) { if (id7 & 1) Sy += s7; else Sx += s7; }
        }

        sS[w][lo2]     = Sx;
        sS[w][lo2 + 1] = Sy;
    }
    __syncwarp();

    // ---- Mq = sum_v S_v * vtab[v] ----
    {
        float mx0 = 0.f, mx1 = 0.f, my0 = 0.f, my1 = 0.f;
        #pragma unroll 8
        for (int vv = 0; vv < VOCAB; vv += 2) {
            float sv0 = sS[w][vv], sv1 = sS[w][vv + 1];
            float2 vt0 = __ldg((const float2*)&g_vtab[vv * H + lo2]);
            float2 vt1 = __ldg((const float2*)&g_vtab[(vv + 1) * H + lo2]);
            mx0 = fmaf(sv0, vt0.x, mx0); my0 = fmaf(sv0, vt0.y, my0);
            mx1 = fmaf(sv1, vt1.x, mx1); my1 = fmaf(sv1, vt1.y, my1);
        }
        // reuse sRi as Mq scratch (done with R-init)
        sRi[w][lo2]     = mx0 + mx1;
        sRi[w][lo2 + 1] = my0 + my1;
    }
    __syncwarp();

    // ---- epilogue: out = Wcomb @ Mq + bcomb ----
    #pragma unroll
    for (int rr = 0; rr < 2; rr++) {
        const int i = lane + 32 * rr;
        const float4* w4 = (const float4*)(g_Wcomb + i * H);
        const float4* m4 = (const float4*)sRi[w];
        float a0 = 0.f, a1 = 0.f, a2 = 0.f, a3 = 0.f;
        #pragma unroll
        for (int j = 0; j < 16; j++) {
            float4 ww = __ldg(w4 + j);
            float4 m = m4[j];
            a0 = fmaf(ww.x, m.x, a0); a1 = fmaf(ww.y, m.y, a1);
            a2 = fmaf(ww.z, m.z, a2); a3 = fmaf(ww.w, m.w, a3);
        }
        out[b * H + i] = (a0 + a1) + (a2 + a3) + g_bcomb[i];
    }

    // ---- reset spin barriers for the next (graph-replayed) launch ----
    __syncthreads();
    if (tid == 0) {
        __threadfence();
        if (atomicAdd(&g_rst, 1u) == (unsigned)(NBLK - 1)) {
            atomicExch(&g_bar1, 0u);
            atomicExch(&g_bar2, 0u);
            atomicExch(&g_rst, 0u);
        }
    }
}

// ======================================================================
extern "C" void kernel_launch(void* const* d_in, const int* in_sizes, int n_in,
                              void* d_out, int out_size)
{
    (void)in_sizes; (void)n_in; (void)out_size;
    const int*   seq   = (const int*)  d_in[0];
    const float* embed = (const float*)d_in[1];
    const float* W1    = (const float*)d_in[2];
    const float* b1    = (const float*)d_in[3];
    const float* W2    = (const float*)d_in[4];
    const float* b2    = (const float*)d_in[5];
    const float* gamma = (const float*)d_in[6];
    const float* beta  = (const float*)d_in[7];
    const float* Wk    = (const float*)d_in[8];
    const float* Wv    = (const float*)d_in[9];
    const float* Wq    = (const float*)d_in[10];
    const float* Wrp   = (const float*)d_in[11];
    const float* brp   = (const float*)d_in[12];
    const float* Wout  = (const float*)d_in[13];
    const float* bout  = (const float*)d_in[14];

    fused_kernel<<<NBLK, 128>>>(seq, embed, W1, b1, W2, b2, gamma, beta,
                                Wk, Wv, Wq, Wrp, brp, Wout, bout,
                                (float*)d_out);
}